// round 9
// baseline (speedup 1.0000x reference)
#include <cuda_runtime.h>
#include <math.h>

#define HH 512
#define WW 512
#define NB 8
#define NIMG 16
#define NBLK 512
#define NTHR 256
#define NW 8             // warps per block
#define PAIRBLK 64       // blocks per image pair (32 per image)
#define FULL 0xffffffffu

// packed thresholded masks: [image][row][16 words of 32 cols] = 512 KB
__device__ unsigned int g_mbits[NIMG][HH][16];
// per-(image, block-slice) nonempty flags (overwritten every replay)
__device__ int g_anyp[NIMG][32];
// running max dt^2 per EDT-image. Reset by finalizer each replay.
__device__ unsigned int g_hmax[NIMG];
// monotonic per-pair barriers + completion counter (grow across replays)
__device__ unsigned int g_pairbar[NB];
__device__ unsigned int g_done = 0;

// nearest set-bit horizontal distance in a 512-bit packed row (clamped 1024)
__device__ __forceinline__ int nearest_dj(const unsigned int* __restrict__ rb, int j) {
    int jw = j >> 5, jb = j & 31;
    unsigned wj = rb[jw];
    int dright = 1 << 20;
    unsigned hi = wj >> jb;
    if (hi) dright = __ffs(hi) - 1;
    else {
        #pragma unroll 4
        for (int w = jw + 1; w < 16; w++) {
            unsigned x = rb[w];
            if (x) { dright = (w << 5) + __ffs(x) - 1 - j; break; }
        }
    }
    int dleft = 1 << 20;
    unsigned lo = jb ? (wj & ((1u << jb) - 1u)) : 0u;
    if (lo) dleft = jb - (31 - __clz(lo));
    else {
        #pragma unroll 4
        for (int w = jw - 1; w >= 0; w--) {
            if ((j - ((w << 5) + 31)) >= dright) break;
            unsigned x = rb[w];
            if (x) { dleft = j - ((w << 5) + 31 - __clz(x)); break; }
        }
    }
    return min(min(dright, dleft), 1024);
}

// exact squared distance for an (astronomically rare) pixel with empty 5x5
__device__ __noinline__ int exact_d2(int im, int row, int j) {
    int best2 = 1 << 19;
    for (int dr = 0; dr < HH; dr++) {
        int dr2 = dr * dr;
        if (dr2 >= best2) break;
        int r = row - dr;
        if (r >= 0) {
            int dj = nearest_dj(g_mbits[im][r], j);
            best2 = min(best2, dr2 + dj * dj);
        }
        if (dr) {
            r = row + dr;
            if (r < HH) {
                int dj = nearest_dj(g_mbits[im][r], j);
                best2 = min(best2, dr2 + dj * dj);
            }
        }
    }
    return best2;
}

__device__ __forceinline__ unsigned nib4(float4 v) {
    return (v.x > 0.5f ? 1u : 0u) | (v.y > 0.5f ? 2u : 0u)
         | (v.z > 0.5f ? 4u : 0u) | (v.w > 0.5f ? 8u : 0u);
}

__device__ __forceinline__ unsigned sh1(unsigned x, unsigned xm, unsigned xp) {
    return ((x << 1) | (xm >> 31)) | ((x >> 1) | (xp << 31));
}
__device__ __forceinline__ unsigned sh2(unsigned x, unsigned xm, unsigned xp) {
    return ((x << 2) | (xm >> 30)) | ((x >> 2) | (xp << 30));
}

__global__ __launch_bounds__(NTHR, 4)
void hausdorff_fused(const float* __restrict__ inA,
                     const float* __restrict__ inB,
                     float* __restrict__ out) {
    __shared__ unsigned char s_nib[NW][128];
    __shared__ int s_red[NW];
    __shared__ unsigned s_old;
    const int t    = threadIdx.x;
    const int w    = t >> 5;
    const int lane = t & 31;
    const int blk  = blockIdx.x;
    // pair-interleaved block->image map: pair q's 64 blocks are contiguous
    const int pr   = blk >> 6;                    // pair id 0..7
    const int im   = pr + (((blk >> 5) & 1) << 3); // image 0..15
    const int ib   = blk & 31;                    // block within image
    const int row0 = (ib * NW + w) * 2;           // 2 rows per warp
    const int half = lane >> 4;                   // which of the 2 rows
    const int wj   = lane & 15;                   // word index within row

    unsigned C;        // this lane's mask word (row row0+half, word wj)
    // ------- Phase 1: coalesced threshold + bit-pack ------------------------
    {
        const float* src = ((im < NB) ? inA : inB) + (size_t)(im & 7) * HH * WW;
        const float4* r0 = (const float4*)(src + (size_t)row0 * WW);
        const float4* r1 = (const float4*)(src + (size_t)(row0 + 1) * WW);
        float4 a0 = r0[lane], a1 = r0[lane + 32], a2 = r0[lane + 64], a3 = r0[lane + 96];
        float4 b0 = r1[lane], b1 = r1[lane + 32], b2 = r1[lane + 64], b3 = r1[lane + 96];

        unsigned char* sn = &s_nib[w][0];
        sn[0 * 32 + lane] = (unsigned char)(nib4(a0) | (nib4(b0) << 4));
        sn[1 * 32 + lane] = (unsigned char)(nib4(a1) | (nib4(b1) << 4));
        sn[2 * 32 + lane] = (unsigned char)(nib4(a2) | (nib4(b2) << 4));
        sn[3 * 32 + lane] = (unsigned char)(nib4(a3) | (nib4(b3) << 4));
        __syncwarp();

        // assemble word (row=half, word=wj) from 8 nibbles
        uint2 v = *(const uint2*)&sn[(wj >> 2) * 32 + (wj & 3) * 8];
        unsigned x = (v.x >> (4 * half)) & 0x0F0F0F0Fu;
        unsigned y = (v.y >> (4 * half)) & 0x0F0F0F0Fu;
        x = (x | (x >> 4)) & 0x00FF00FFu;  x = (x | (x >> 8)) & 0x0000FFFFu;
        y = (y | (y >> 4)) & 0x00FF00FFu;  y = (y | (y >> 8)) & 0x0000FFFFu;
        C = x | (y << 16);
        g_mbits[im][row0 + half][wj] = C;

        int anyb = __syncthreads_or(C != 0u);
        if (t == 0) g_anyp[im][ib] = anyb;
    }

    // ------- per-pair barrier (64 blocks: both images of this pair) ---------
    {
        if (t == 0) {
            __threadfence();
            unsigned old = atomicAdd(&g_pairbar[pr], 1u);
            unsigned target = (old / PAIRBLK + 1u) * PAIRBLK;
            while (*(volatile unsigned int*)&g_pairbar[pr] < target) { }
            __threadfence();
        }
        __syncthreads();
    }

    // ------- Phase 2: 5x5 tiered exact Hausdorff max ------------------------
    {
        const int row = row0 + half;
        const int oim = im ^ 8;
        unsigned peer = __shfl_xor_sync(FULL, C, 16);   // the other row's word

        unsigned U1 = half ? peer : (row > 0 ? g_mbits[im][row - 1][wj] : 0u);
        unsigned D1 = half ? (row < HH - 1 ? g_mbits[im][row + 1][wj] : 0u) : peer;
        unsigned U2 = (row > 1)      ? g_mbits[im][row - 2][wj] : 0u;
        unsigned D2 = (row < HH - 2) ? g_mbits[im][row + 2][wj] : 0u;
        unsigned G  = g_mbits[oim][row][wj];

        unsigned Cm  = __shfl_sync(FULL, C,  (lane + 31) & 31);
        unsigned Cp  = __shfl_sync(FULL, C,  (lane + 1) & 31);
        unsigned U1m = __shfl_sync(FULL, U1, (lane + 31) & 31);
        unsigned U1p = __shfl_sync(FULL, U1, (lane + 1) & 31);
        unsigned D1m = __shfl_sync(FULL, D1, (lane + 31) & 31);
        unsigned D1p = __shfl_sync(FULL, D1, (lane + 1) & 31);
        unsigned U2m = __shfl_sync(FULL, U2, (lane + 31) & 31);
        unsigned U2p = __shfl_sync(FULL, U2, (lane + 1) & 31);
        unsigned D2m = __shfl_sync(FULL, D2, (lane + 31) & 31);
        unsigned D2p = __shfl_sync(FULL, D2, (lane + 1) & 31);
        if (wj == 0)  { Cm = 0u; U1m = 0u; D1m = 0u; U2m = 0u; D2m = 0u; }
        if (wj == 15) { Cp = 0u; U1p = 0u; D1p = 0u; U2p = 0u; D2p = 0u; }

        unsigned t0 = C;
        unsigned t1 = sh1(C, Cm, Cp) | U1 | D1;
        unsigned t2 = sh1(U1, U1m, U1p) | sh1(D1, D1m, D1p);
        unsigned t4 = sh2(C, Cm, Cp) | U2 | D2;
        unsigned t5 = sh2(U1, U1m, U1p) | sh2(D1, D1m, D1p)
                    | sh1(U2, U2m, U2p) | sh1(D2, D2m, D2p);
        unsigned t8 = sh2(U2, U2m, U2p) | sh2(D2, D2m, D2p);

        unsigned n1 = t0 | t1;
        unsigned n2 = n1 | t2;
        unsigned n4 = n2 | t4;
        unsigned n5 = n4 | t5;
        unsigned n8 = n5 | t8;

        int v = 0;
        if (G & t1 & ~t0) v = 1;
        if (G & t2 & ~n1) v = 2;
        if (G & t4 & ~n2) v = 4;
        if (G & t5 & ~n4) v = 5;
        if (G & t8 & ~n5) v = 8;

        unsigned leftover = G & ~n8;          // p ~ 2^-25 per gated pixel
        int j0 = wj * 32;
        while (leftover) {
            int bbit = __ffs(leftover) - 1;
            leftover &= leftover - 1u;
            v = max(v, exact_d2(im, row, j0 + bbit));
        }

        #pragma unroll
        for (int o = 16; o > 0; o >>= 1)
            v = max(v, __shfl_down_sync(FULL, v, o));
        if (lane == 0) s_red[w] = v;
        __syncthreads();
        if (t == 0) {
            int m = s_red[0];
            #pragma unroll
            for (int k = 1; k < NW; k++) m = max(m, s_red[k]);
            atomicMax(&g_hmax[im], (unsigned)m);
        }
    }

    // ------- completion: LAST-arriving block finalizes ----------------------
    __syncthreads();
    if (t == 0) {
        __threadfence();
        s_old = atomicAdd(&g_done, 1u);
    }
    __syncthreads();
    if (((s_old + 1u) % NBLK) != 0u) return;   // exactly one block per replay

    if (t < 32) {
        float term = 0.0f;
        unsigned h2u = 0u;
        int anyA = 0, anyB = 0;
        if (t < NB) {
            h2u = max(g_hmax[t], g_hmax[t + 8]);
            #pragma unroll
            for (int k = 0; k < 32; k++) {
                anyA |= g_anyp[t][k];
                anyB |= g_anyp[t + 8][k];
            }
        }
        __syncwarp();
        if (t < NIMG) g_hmax[t] = 0u;        // reset for next replay
        if (t < NB) {
            bool empty = !(anyA && anyB);
            float hd = sqrtf((float)h2u);
            term = empty ? 1.0f : (1.0f - 1.0f / (1.0f + hd));
        }
        #pragma unroll
        for (int o = 16; o > 0; o >>= 1)
            term += __shfl_down_sync(FULL, term, o);
        if (t == 0) out[0] = term / (float)NB;
    }
}

extern "C" void kernel_launch(void* const* d_in, const int* in_sizes, int n_in,
                              void* d_out, int out_size) {
    const float* inputs  = (const float*)d_in[0];
    const float* targets = (const float*)d_in[1];
    float* out = (float*)d_out;
    hausdorff_fused<<<NBLK, NTHR>>>(inputs, targets, out);
}